// round 15
// baseline (speedup 1.0000x reference)
#include <cuda_runtime.h>
#include <cuda_fp16.h>

#define NN 100000
#define NE 1600000
#define FIN 128
#define HID 64
#define SCAN_NBLK 98     // CSR-role blocks (scan chunk count: ceil(NN/1024))
#define ALL_B 148
#define GEMM_BLKS (ALL_B - SCAN_NBLK)   // 50 GEMM-role blocks
#define NTILES ((NN + 63) / 64)         // 1563 64-row tiles
#define PGRID 296                        // persistent grid for gemm2/head
#define ZROW (NN * 32)                   // pre-scaled index of the zero row

typedef unsigned int uint32;

// ---------------- scratch (device globals; no allocation allowed) ----------------
__device__ __align__(256) __half2 g_h0h[(size_t)(NN + 1) * 32];  // +1 zero row for pads
__device__ __align__(256) __half2 g_h1h[(size_t)NN * 32];
__device__ __align__(256) __half  g_yh[(size_t)NN * 16];         // edge-head partials (fp16)
__device__ __align__(256) float  g_dinv[NN];
__device__ __align__(256) int    g_deg[NN];                // zeroed by k_edge for next replay
__device__ __align__(256) int    g_rank[NE];
__device__ __align__(256) int    g_rowptr[NN + 1];
__device__ __align__(256) int    g_src[NE + 4 * NN];       // padded payload: src*32
__device__ __align__(256) int    g_bsums[128];
__device__ int g_barc[8];   // barrier counters (zeroed by k_edge)

// ---------------- software grid barrier (CSR-role blocks only: target 98) ----------------
__device__ __forceinline__ void gbar(int j) {
    __syncthreads();
    if (threadIdx.x == 0) {
        __threadfence();
        atomicAdd(&g_barc[j], 1);
        volatile int* p = &g_barc[j];
        while (*p < SCAN_NBLK) { }
        __threadfence();
    }
    __syncthreads();
}

__device__ __forceinline__ void mma16816(float d[4], uint32 a0, uint32 a1, uint32 a2,
                                         uint32 a3, uint32 b0, uint32 b1) {
    asm volatile(
        "mma.sync.aligned.m16n8k16.row.col.f32.f16.f16.f32 "
        "{%0,%1,%2,%3}, {%4,%5,%6,%7}, {%8,%9}, {%0,%1,%2,%3};"
        : "+f"(d[0]), "+f"(d[1]), "+f"(d[2]), "+f"(d[3])
        : "r"(a0), "r"(a1), "r"(a2), "r"(a3), "r"(b0), "r"(b1));
}

// ---------------- histogram + rank (full chip; deg zero on entry) ----------------
__global__ __launch_bounds__(1024) void k_hist(const int* __restrict__ col) {
    int gt = blockIdx.x * 1024 + threadIdx.x;
    for (int e = gt; e < NE; e += ALL_B * 1024)
        g_rank[e] = atomicAdd(&g_deg[col[e]], 1);
    if (blockIdx.x == 0 && threadIdx.x < 32)
        reinterpret_cast<uint32*>(g_h0h)[ZROW + threadIdx.x] = 0;
}

// ============ fused: blocks 0..97 scan+fill (padded), blocks 98..147 premul GEMM1 ============
extern __shared__ __half dsm_[];

__global__ __launch_bounds__(1024, 1) void k_scan_gemm(const int* __restrict__ row,
                                                       const int* __restrict__ col,
                                                       const float* __restrict__ x,
                                                       const float* __restrict__ W1) {
    const int tid = threadIdx.x, bid = blockIdx.x;

    if (bid >= SCAN_NBLK) {
        // ------------- GEMM1 role: g_h0h = fp16(dinv * (x @ W1)) -------------
        __half (*Wt)[FIN + 8]  = reinterpret_cast<__half(*)[FIN + 8]>(dsm_);
        __half (*Ahs)[FIN + 8] = reinterpret_cast<__half(*)[FIN + 8]>(dsm_) + 64;

        for (int i = tid; i < FIN * 64; i += 1024) {
            int k = i >> 6, n = i & 63;
            Wt[n][k] = __float2half(W1[i]);
        }
        __syncthreads();

        const int g = tid >> 7;
        const int t = tid & 127;
        const int warp = t >> 5, lane = t & 31;
        const int gr = lane >> 2;
        const int kc = (lane & 3) * 2;
        __half (*Ag)[FIN + 8] = Ahs + g * 64;
        const int barid = g + 1;

        for (int tile = (bid - SCAN_NBLK) * 8 + g; tile < NTILES; tile += GEMM_BLKS * 8) {
            const int rbase = tile * 64;
            #pragma unroll
            for (int it = 0; it < 16; it++) {
                int i = it * 128 + t;
                int r = i >> 5, v = i & 31;
                int R = rbase + r;
                float4 f = make_float4(0.f, 0.f, 0.f, 0.f);
                if (R < NN) f = reinterpret_cast<const float4*>(x + (size_t)R * FIN)[v];
                __half2 h01 = __floats2half2_rn(f.x, f.y);
                __half2 h23 = __floats2half2_rn(f.z, f.w);
                uint2 pk = make_uint2(*reinterpret_cast<uint32*>(&h01),
                                      *reinterpret_cast<uint32*>(&h23));
                *reinterpret_cast<uint2*>(&Ag[r][v * 4]) = pk;
            }
            asm volatile("bar.sync %0, 128;" :: "r"(barid) : "memory");

            const int lr0 = warp * 16 + gr, lr1 = lr0 + 8;
            const int R0 = rbase + lr0, R1 = rbase + lr1;
            float d[8][4];
            #pragma unroll
            for (int nt = 0; nt < 8; nt++)
                #pragma unroll
                for (int q = 0; q < 4; q++) d[nt][q] = 0.f;

            #pragma unroll
            for (int q = 0; q < FIN / 16; q++) {
                int k0 = q * 16 + kc;
                uint32 a0 = *reinterpret_cast<const uint32*>(&Ag[lr0][k0]);
                uint32 a1 = *reinterpret_cast<const uint32*>(&Ag[lr1][k0]);
                uint32 a2 = *reinterpret_cast<const uint32*>(&Ag[lr0][k0 + 8]);
                uint32 a3 = *reinterpret_cast<const uint32*>(&Ag[lr1][k0 + 8]);
                #pragma unroll
                for (int nt = 0; nt < 8; nt++) {
                    int n = nt * 8 + gr;
                    uint32 b0 = *reinterpret_cast<const uint32*>(&Wt[n][k0]);
                    uint32 b1 = *reinterpret_cast<const uint32*>(&Wt[n][k0 + 8]);
                    mma16816(d[nt], a0, a1, a2, a3, b0, b1);
                }
            }

            float dv0 = (R0 < NN) ? rsqrtf((float)__ldcg(&g_deg[R0]) + 1.0f) : 0.f;
            float dv1 = (R1 < NN) ? rsqrtf((float)__ldcg(&g_deg[R1]) + 1.0f) : 0.f;
            #pragma unroll
            for (int nt = 0; nt < 8; nt++) {
                int c = nt * 8 + kc;
                *reinterpret_cast<__half2*>(&Ag[lr0][c]) =
                    __floats2half2_rn(d[nt][0] * dv0, d[nt][1] * dv0);
                *reinterpret_cast<__half2*>(&Ag[lr1][c]) =
                    __floats2half2_rn(d[nt][2] * dv1, d[nt][3] * dv1);
            }
            __syncwarp();
            __half* outp = reinterpret_cast<__half*>(g_h0h);
            #pragma unroll
            for (int rr = 0; rr < 16; rr++) {
                int R = rbase + warp * 16 + rr;
                if (R < NN) {
                    uint32 v = reinterpret_cast<const uint32*>(&Ag[warp * 16 + rr][0])[lane];
                    reinterpret_cast<uint32*>(outp + (size_t)R * 64)[lane] = v;
                }
            }
            asm volatile("bar.sync %0, 128;" :: "r"(barid) : "memory");
        }
        return;
    }

    // ---------------- CSR role: dinv + padded scan + fill ----------------
    int excl = 0;
    int valid = 0;
    int v = 0, pv = 0;
    {
        int i = bid * 1024 + tid;
        valid = (i < NN);
        v = valid ? __ldcg(&g_deg[i]) : 0;
        pv = (v + 3) & ~3;
        if (valid) g_dinv[i] = rsqrtf((float)v + 1.0f);   // +1 self-loop
        int lane = tid & 31, wid = tid >> 5;
        int xs = pv;
        #pragma unroll
        for (int dd = 1; dd < 32; dd <<= 1) {
            int y = __shfl_up_sync(0xffffffffu, xs, dd);
            if (lane >= dd) xs += y;
        }
        __shared__ int wsum[32];
        if (lane == 31) wsum[wid] = xs;
        __syncthreads();
        if (wid == 0) {
            int s = wsum[lane];
            int sx = s;
            #pragma unroll
            for (int dd = 1; dd < 32; dd <<= 1) {
                int y = __shfl_up_sync(0xffffffffu, sx, dd);
                if (lane >= dd) sx += y;
            }
            wsum[lane] = sx - s;
        }
        __syncthreads();
        int incl = xs + wsum[wid];
        excl = incl - pv;
        if (tid == 1023) g_bsums[bid] = incl;
    }
    gbar(0);

    {
        __shared__ int ws[4];
        int bv = 0, incl = 0;
        if (bid == 0) {
            if (tid < 128) {
                bv = (tid < SCAN_NBLK) ? __ldcg(&g_bsums[tid]) : 0;
                int lane = tid & 31, wid = tid >> 5;
                int xs = bv;
                #pragma unroll
                for (int dd = 1; dd < 32; dd <<= 1) {
                    int y = __shfl_up_sync(0xffffffffu, xs, dd);
                    if (lane >= dd) xs += y;
                }
                if (lane == 31) ws[wid] = xs;
                incl = xs;
            }
            __syncthreads();
            if (tid < 128) {
                int wid = tid >> 5;
                int off = 0;
                for (int w = 0; w < wid; w++) off += ws[w];
                incl += off;
                if (tid < SCAN_NBLK) g_bsums[tid] = incl - bv;
            }
        }
    }
    gbar(1);

    if (valid) {
        int i = bid * 1024 + tid;
        int rp = excl + __ldcg(&g_bsums[bid]);
        g_rowptr[i] = rp;
        for (int j = v; j < pv; j++) g_src[rp + j] = ZROW;   // pad slots -> zero row
        if (i == NN - 1) g_rowptr[NN] = rp + pv;
    }
    gbar(2);

    const int gt = bid * 1024 + tid;
    for (int e = gt; e < NE; e += SCAN_NBLK * 1024) {
        int c = col[e];
        int p = __ldcg(&g_rowptr[c]) + __ldcg(&g_rank[e]);
        g_src[p] = row[e] << 5;
    }
}

// ---------------- conv2 GEMM (persistent blocks; W staged ONCE per block) ----------------
__global__ __launch_bounds__(128) void k_gemm2(const float* __restrict__ W) {
    __shared__ __half Wt[64][HID + 8];
    __shared__ __half Ahs[64][HID + 8];

    for (int i = threadIdx.x; i < HID * 64; i += 128) {
        int k = i >> 6, n = i & 63;
        Wt[n][k] = __float2half(W[i]);
    }
    __syncthreads();

    const int warp = threadIdx.x >> 5, lane = threadIdx.x & 31;
    const int gr = lane >> 2;
    const int kc = (lane & 3) * 2;
    const __half* Ah = reinterpret_cast<const __half*>(g_h1h);
    __half* outp = reinterpret_cast<__half*>(g_h0h);

    for (int tile = blockIdx.x; tile < NTILES; tile += PGRID) {
        const int rbase = tile * 64;
        #pragma unroll
        for (int it = 0; it < 4; it++) {
            int i = it * 128 + threadIdx.x;
            int r = i >> 3, v = i & 7;
            int R = rbase + r;
            uint4 val = make_uint4(0, 0, 0, 0);
            if (R < NN) val = reinterpret_cast<const uint4*>(Ah + (size_t)R * HID)[v];
            reinterpret_cast<uint4*>(&Ahs[r][0])[v] = val;
        }
        __syncthreads();

        const int lr0 = warp * 16 + gr, lr1 = lr0 + 8;
        const int R0 = rbase + lr0, R1 = rbase + lr1;

        float d[8][4];
        #pragma unroll
        for (int nt = 0; nt < 8; nt++)
            #pragma unroll
            for (int q = 0; q < 4; q++) d[nt][q] = 0.f;

        #pragma unroll
        for (int q = 0; q < HID / 16; q++) {
            int k0 = q * 16 + kc;
            uint32 a0 = *reinterpret_cast<const uint32*>(&Ahs[lr0][k0]);
            uint32 a1 = *reinterpret_cast<const uint32*>(&Ahs[lr1][k0]);
            uint32 a2 = *reinterpret_cast<const uint32*>(&Ahs[lr0][k0 + 8]);
            uint32 a3 = *reinterpret_cast<const uint32*>(&Ahs[lr1][k0 + 8]);
            #pragma unroll
            for (int nt = 0; nt < 8; nt++) {
                int n = nt * 8 + gr;
                uint32 b0 = *reinterpret_cast<const uint32*>(&Wt[n][k0]);
                uint32 b1 = *reinterpret_cast<const uint32*>(&Wt[n][k0 + 8]);
                mma16816(d[nt], a0, a1, a2, a3, b0, b1);
            }
        }

        float dv0 = (R0 < NN) ? g_dinv[R0] : 0.f;
        float dv1 = (R1 < NN) ? g_dinv[R1] : 0.f;
        __syncthreads();   // protect Ahs reuse (epilogue staging)
        #pragma unroll
        for (int nt = 0; nt < 8; nt++) {
            int c = nt * 8 + kc;
            *reinterpret_cast<__half2*>(&Ahs[lr0][c]) =
                __floats2half2_rn(d[nt][0] * dv0, d[nt][1] * dv0);
            *reinterpret_cast<__half2*>(&Ahs[lr1][c]) =
                __floats2half2_rn(d[nt][2] * dv1, d[nt][3] * dv1);
        }
        __syncwarp();
        #pragma unroll
        for (int rr = 0; rr < 16; rr++) {
            int R = rbase + warp * 16 + rr;
            if (R < NN) {
                uint32 v = reinterpret_cast<const uint32*>(&Ahs[warp * 16 + rr][0])[lane];
                reinterpret_cast<uint32*>(outp + (size_t)R * 64)[lane] = v;
            }
        }
        __syncthreads();   // Ahs free for next tile stage
    }
}

// ---------------- GCN aggregate (unweighted, padded rows, HADD2 pairing) ----------------
__global__ __launch_bounds__(256) void k_agg(const float* __restrict__ bias) {
    int gw = (blockIdx.x * 256 + threadIdx.x) >> 5;
    int lane = threadIdx.x & 31;
    float di = g_dinv[gw];
    int beg = g_rowptr[gw], end = g_rowptr[gw + 1];   // 4-aligned

    const __half2* hin = g_h0h;
    float2 hself = __half22float2(hin[gw * 32 + lane]);
    float ax = hself.x, ay = hself.y;

    int e = beg;
    for (; e + 8 <= end; e += 8) {
        int4 pa = *reinterpret_cast<const int4*>(&g_src[e]);
        int4 pb = *reinterpret_cast<const int4*>(&g_src[e + 4]);
        __half2 v0 = __ldg(&hin[pa.x + lane]);
        __half2 v1 = __ldg(&hin[pa.y + lane]);
        __half2 v2 = __ldg(&hin[pa.z + lane]);
        __half2 v3 = __ldg(&hin[pa.w + lane]);
        __half2 v4 = __ldg(&hin[pb.x + lane]);
        __half2 v5 = __ldg(&hin[pb.y + lane]);
        __half2 v6 = __ldg(&hin[pb.z + lane]);
        __half2 v7 = __ldg(&hin[pb.w + lane]);
        float2 s0 = __half22float2(__hadd2(v0, v1));
        float2 s1 = __half22float2(__hadd2(v2, v3));
        float2 s2 = __half22float2(__hadd2(v4, v5));
        float2 s3 = __half22float2(__hadd2(v6, v7));
        ax += (s0.x + s1.x) + (s2.x + s3.x);
        ay += (s0.y + s1.y) + (s2.y + s3.y);
    }
    if (e < end) {
        int4 pa = *reinterpret_cast<const int4*>(&g_src[e]);
        __half2 v0 = __ldg(&hin[pa.x + lane]);
        __half2 v1 = __ldg(&hin[pa.y + lane]);
        __half2 v2 = __ldg(&hin[pa.z + lane]);
        __half2 v3 = __ldg(&hin[pa.w + lane]);
        float2 s0 = __half22float2(__hadd2(v0, v1));
        float2 s1 = __half22float2(__hadd2(v2, v3));
        ax += s0.x + s1.x;
        ay += s0.y + s1.y;
    }
    float2 b = reinterpret_cast<const float2*>(bias)[lane];
    float rx = fmaxf(fmaf(di, ax, b.x), 0.f);
    float ry = fmaxf(fmaf(di, ay, b.y), 0.f);
    g_h1h[gw * 32 + lane] = __floats2half2_rn(rx, ry);
}

// ---------------- edge head GEMM (persistent): g_yh[r,16](fp16) = h2@Wm (+bl cols 0..7) ----------------
__global__ __launch_bounds__(128) void k_head(const float* __restrict__ Wl,
                                              const float* __restrict__ bl) {
    __shared__ __half Wt[16][HID + 8];
    __shared__ __half Ahs[64][HID + 8];

    for (int i = threadIdx.x; i < 16 * 64; i += 128) {
        int o = i >> 6, k = i & 63;
        float wv = (o < 8) ? Wl[k * 8 + o] : Wl[(64 + k) * 8 + (o - 8)];
        Wt[o][k] = __float2half(wv);
    }
    __syncthreads();

    const int warp = threadIdx.x >> 5, lane = threadIdx.x & 31;
    const int gr = lane >> 2;
    const int kc = (lane & 3) * 2;
    const __half* Ah = reinterpret_cast<const __half*>(g_h1h);
    const float bx0 = __ldg(&bl[kc]), bx1 = __ldg(&bl[kc + 1]);

    for (int tile = blockIdx.x; tile < NTILES; tile += PGRID) {
        const int rbase = tile * 64;
        #pragma unroll
        for (int it = 0; it < 4; it++) {
            int i = it * 128 + threadIdx.x;
            int r = i >> 3, v = i & 7;
            int R = rbase + r;
            uint4 val = make_uint4(0, 0, 0, 0);
            if (R < NN) val = reinterpret_cast<const uint4*>(Ah + (size_t)R * HID)[v];
            reinterpret_cast<uint4*>(&Ahs[r][0])[v] = val;
        }
        __syncthreads();

        const int lr0 = warp * 16 + gr, lr1 = lr0 + 8;
        const int R0 = rbase + lr0, R1 = rbase + lr1;

        float d[2][4];
        #pragma unroll
        for (int nt = 0; nt < 2; nt++)
            #pragma unroll
            for (int q = 0; q < 4; q++) d[nt][q] = 0.f;

        #pragma unroll
        for (int q = 0; q < HID / 16; q++) {
            int k0 = q * 16 + kc;
            uint32 a0 = *reinterpret_cast<const uint32*>(&Ahs[lr0][k0]);
            uint32 a1 = *reinterpret_cast<const uint32*>(&Ahs[lr1][k0]);
            uint32 a2 = *reinterpret_cast<const uint32*>(&Ahs[lr0][k0 + 8]);
            uint32 a3 = *reinterpret_cast<const uint32*>(&Ahs[lr1][k0 + 8]);
            #pragma unroll
            for (int nt = 0; nt < 2; nt++) {
                int n = nt * 8 + gr;
                uint32 b0 = *reinterpret_cast<const uint32*>(&Wt[n][k0]);
                uint32 b1 = *reinterpret_cast<const uint32*>(&Wt[n][k0 + 8]);
                mma16816(d[nt], a0, a1, a2, a3, b0, b1);
            }
        }

        if (R0 < NN) {
            *reinterpret_cast<__half2*>(&g_yh[(size_t)R0 * 16 + kc]) =
                __floats2half2_rn(d[0][0] + bx0, d[0][1] + bx1);
            *reinterpret_cast<__half2*>(&g_yh[(size_t)R0 * 16 + 8 + kc]) =
                __floats2half2_rn(d[1][0], d[1][1]);
        }
        if (R1 < NN) {
            *reinterpret_cast<__half2*>(&g_yh[(size_t)R1 * 16 + kc]) =
                __floats2half2_rn(d[0][2] + bx0, d[0][3] + bx1);
            *reinterpret_cast<__half2*>(&g_yh[(size_t)R1 * 16 + 8 + kc]) =
                __floats2half2_rn(d[1][2], d[1][3]);
        }
        __syncthreads();   // Ahs reuse
    }
}

// ---------------- edge phase (fp16 y) + state cleanup for next replay ----------------
__global__ void k_edge(const int* __restrict__ row, const int* __restrict__ col,
                       float* __restrict__ out) {
    int idx = blockIdx.x * 256 + threadIdx.x;
    if (idx < NN) g_deg[idx] = 0;
    if (idx < 8) g_barc[idx] = 0;
    if (idx >= NE * 2) return;
    int e = idx >> 1, c = idx & 1;
    int r = row[e], cl = col[e];
    const __half2* a2 = reinterpret_cast<const __half2*>(&g_yh[(size_t)r * 16 + c * 4]);
    const __half2* b2 = reinterpret_cast<const __half2*>(&g_yh[(size_t)cl * 16 + 8 + c * 4]);
    __half2 a0 = a2[0], a1 = a2[1];
    __half2 b0 = b2[0], b1 = b2[1];
    float2 fa0 = __half22float2(a0), fa1 = __half22float2(a1);
    float2 fb0 = __half22float2(b0), fb1 = __half22float2(b1);
    float4 o;
    o.x = fa0.x + fb0.x;
    o.y = fa0.y + fb0.y;
    o.z = fa1.x + fb1.x;
    o.w = fa1.y + fb1.y;
    reinterpret_cast<float4*>(out)[idx] = o;
}

// ---------------- launch ----------------
extern "C" void kernel_launch(void* const* d_in, const int* in_sizes, int n_in,
                              void* d_out, int out_size) {
    const float* x  = (const float*)d_in[0];
    const int*   ei = (const int*)  d_in[1];
    const float* W1 = (const float*)d_in[2];
    const float* b1 = (const float*)d_in[3];
    const float* W2 = (const float*)d_in[4];
    const float* b2 = (const float*)d_in[5];
    const float* Wl = (const float*)d_in[6];
    const float* bl = (const float*)d_in[7];
    float* out = (float*)d_out;

    const int* row = ei;        // edge_index[0]
    const int* col = ei + NE;   // edge_index[1]

    const int DSMEM = (64 + 8 * 64) * (FIN + 8) * (int)sizeof(__half);  // 156,672 B
    static bool attr_set = false;
    if (!attr_set) {
        cudaFuncSetAttribute(k_scan_gemm, cudaFuncAttributeMaxDynamicSharedMemorySize, DSMEM);
        attr_set = true;
    }

    // hist + rank (deg zeroed by previous k_edge / initial state)
    k_hist<<<ALL_B, 1024>>>(col);

    // fused: padded scan+fill (0..97) + premultiplied GEMM1 (98..147)
    k_scan_gemm<<<ALL_B, 1024, DSMEM>>>(row, col, x, W1);

    // conv1 agg -> h1h
    k_agg<<<(NN * 32) / 256, 256>>>(b1);

    // conv2: persistent premultiplied GEMM (h1h -> h0h) + agg (-> h1h)
    k_gemm2<<<PGRID, 128>>>(W2);
    k_agg<<<(NN * 32) / 256, 256>>>(b2);

    // persistent edge head GEMM (h1h -> yh fp16), then per-edge sum (+cleanup)
    k_head<<<PGRID, 128>>>(Wl, bl);
    k_edge<<<(NE * 2 + 255) / 256, 256>>>(row, col, out);
}

// round 16
// speedup vs baseline: 1.0149x; 1.0149x over previous
#include <cuda_runtime.h>
#include <cuda_fp16.h>

#define NN 100000
#define NE 1600000
#define FIN 128
#define HID 64
#define SCAN_NBLK 98     // CSR-role blocks (scan chunk count: ceil(NN/1024))
#define ALL_B 148
#define GEMM_BLKS (ALL_B - SCAN_NBLK)   // 50 GEMM-role blocks
#define NTILES ((NN + 63) / 64)         // 1563 64-row tiles
#define ZROW (NN * 32)                   // pre-scaled index of the zero row

typedef unsigned int uint32;

// ---------------- scratch (device globals; no allocation allowed) ----------------
__device__ __align__(256) __half2 g_h0h[(size_t)(NN + 1) * 32];  // +1 zero row for pads
__device__ __align__(256) __half2 g_h1h[(size_t)NN * 32];
__device__ __align__(256) __half  g_yh[(size_t)NN * 16];         // edge-head partials (fp16)
__device__ __align__(256) float  g_dinv[NN];
__device__ __align__(256) int    g_deg[NN];                // zeroed by k_edge for next replay
__device__ __align__(256) int    g_rank[NE];
__device__ __align__(256) int    g_rowptr[NN + 1];
__device__ __align__(256) int    g_src[NE + 4 * NN];       // padded payload: src*32
__device__ __align__(256) int    g_bsums[128];
__device__ int g_barc[8];   // barrier counters (zeroed by k_edge)

// ---------------- software grid barrier (CSR-role blocks only: target 98) ----------------
__device__ __forceinline__ void gbar(int j) {
    __syncthreads();
    if (threadIdx.x == 0) {
        __threadfence();
        atomicAdd(&g_barc[j], 1);
        volatile int* p = &g_barc[j];
        while (*p < SCAN_NBLK) { }
        __threadfence();
    }
    __syncthreads();
}

__device__ __forceinline__ void mma16816(float d[4], uint32 a0, uint32 a1, uint32 a2,
                                         uint32 a3, uint32 b0, uint32 b1) {
    asm volatile(
        "mma.sync.aligned.m16n8k16.row.col.f32.f16.f16.f32 "
        "{%0,%1,%2,%3}, {%4,%5,%6,%7}, {%8,%9}, {%0,%1,%2,%3};"
        : "+f"(d[0]), "+f"(d[1]), "+f"(d[2]), "+f"(d[3])
        : "r"(a0), "r"(a1), "r"(a2), "r"(a3), "r"(b0), "r"(b1));
}

// ---------------- histogram + rank (full chip; deg zero on entry) ----------------
__global__ __launch_bounds__(1024) void k_hist(const int* __restrict__ col) {
    int gt = blockIdx.x * 1024 + threadIdx.x;
    for (int e = gt; e < NE; e += ALL_B * 1024)
        g_rank[e] = atomicAdd(&g_deg[col[e]], 1);
    if (blockIdx.x == 0 && threadIdx.x < 32)
        reinterpret_cast<uint32*>(g_h0h)[ZROW + threadIdx.x] = 0;
}

// ============ fused: blocks 0..97 scan+fill (padded), blocks 98..147 premul GEMM1 ============
extern __shared__ __half dsm_[];

__global__ __launch_bounds__(1024, 1) void k_scan_gemm(const int* __restrict__ row,
                                                       const int* __restrict__ col,
                                                       const float* __restrict__ x,
                                                       const float* __restrict__ W1) {
    const int tid = threadIdx.x, bid = blockIdx.x;

    if (bid >= SCAN_NBLK) {
        // ------------- GEMM1 role: g_h0h = fp16(dinv * (x @ W1)) -------------
        __half (*Wt)[FIN + 8]  = reinterpret_cast<__half(*)[FIN + 8]>(dsm_);
        __half (*Ahs)[FIN + 8] = reinterpret_cast<__half(*)[FIN + 8]>(dsm_) + 64;

        for (int i = tid; i < FIN * 64; i += 1024) {
            int k = i >> 6, n = i & 63;
            Wt[n][k] = __float2half(W1[i]);
        }
        __syncthreads();

        const int g = tid >> 7;
        const int t = tid & 127;
        const int warp = t >> 5, lane = t & 31;
        const int gr = lane >> 2;
        const int kc = (lane & 3) * 2;
        __half (*Ag)[FIN + 8] = Ahs + g * 64;
        const int barid = g + 1;

        for (int tile = (bid - SCAN_NBLK) * 8 + g; tile < NTILES; tile += GEMM_BLKS * 8) {
            const int rbase = tile * 64;
            #pragma unroll
            for (int it = 0; it < 16; it++) {
                int i = it * 128 + t;
                int r = i >> 5, v = i & 31;
                int R = rbase + r;
                float4 f = make_float4(0.f, 0.f, 0.f, 0.f);
                if (R < NN) f = reinterpret_cast<const float4*>(x + (size_t)R * FIN)[v];
                __half2 h01 = __floats2half2_rn(f.x, f.y);
                __half2 h23 = __floats2half2_rn(f.z, f.w);
                uint2 pk = make_uint2(*reinterpret_cast<uint32*>(&h01),
                                      *reinterpret_cast<uint32*>(&h23));
                *reinterpret_cast<uint2*>(&Ag[r][v * 4]) = pk;
            }
            asm volatile("bar.sync %0, 128;" :: "r"(barid) : "memory");

            const int lr0 = warp * 16 + gr, lr1 = lr0 + 8;
            const int R0 = rbase + lr0, R1 = rbase + lr1;
            float d[8][4];
            #pragma unroll
            for (int nt = 0; nt < 8; nt++)
                #pragma unroll
                for (int q = 0; q < 4; q++) d[nt][q] = 0.f;

            #pragma unroll
            for (int q = 0; q < FIN / 16; q++) {
                int k0 = q * 16 + kc;
                uint32 a0 = *reinterpret_cast<const uint32*>(&Ag[lr0][k0]);
                uint32 a1 = *reinterpret_cast<const uint32*>(&Ag[lr1][k0]);
                uint32 a2 = *reinterpret_cast<const uint32*>(&Ag[lr0][k0 + 8]);
                uint32 a3 = *reinterpret_cast<const uint32*>(&Ag[lr1][k0 + 8]);
                #pragma unroll
                for (int nt = 0; nt < 8; nt++) {
                    int n = nt * 8 + gr;
                    uint32 b0 = *reinterpret_cast<const uint32*>(&Wt[n][k0]);
                    uint32 b1 = *reinterpret_cast<const uint32*>(&Wt[n][k0 + 8]);
                    mma16816(d[nt], a0, a1, a2, a3, b0, b1);
                }
            }

            float dv0 = (R0 < NN) ? rsqrtf((float)__ldcg(&g_deg[R0]) + 1.0f) : 0.f;
            float dv1 = (R1 < NN) ? rsqrtf((float)__ldcg(&g_deg[R1]) + 1.0f) : 0.f;
            #pragma unroll
            for (int nt = 0; nt < 8; nt++) {
                int c = nt * 8 + kc;
                *reinterpret_cast<__half2*>(&Ag[lr0][c]) =
                    __floats2half2_rn(d[nt][0] * dv0, d[nt][1] * dv0);
                *reinterpret_cast<__half2*>(&Ag[lr1][c]) =
                    __floats2half2_rn(d[nt][2] * dv1, d[nt][3] * dv1);
            }
            __syncwarp();
            __half* outp = reinterpret_cast<__half*>(g_h0h);
            #pragma unroll
            for (int rr = 0; rr < 16; rr++) {
                int R = rbase + warp * 16 + rr;
                if (R < NN) {
                    uint32 v = reinterpret_cast<const uint32*>(&Ag[warp * 16 + rr][0])[lane];
                    reinterpret_cast<uint32*>(outp + (size_t)R * 64)[lane] = v;
                }
            }
            asm volatile("bar.sync %0, 128;" :: "r"(barid) : "memory");
        }
        return;
    }

    // ---------------- CSR role: dinv + padded scan + fill ----------------
    int excl = 0;
    int valid = 0;
    int v = 0, pv = 0;
    {
        int i = bid * 1024 + tid;
        valid = (i < NN);
        v = valid ? __ldcg(&g_deg[i]) : 0;
        pv = (v + 3) & ~3;
        if (valid) g_dinv[i] = rsqrtf((float)v + 1.0f);   // +1 self-loop
        int lane = tid & 31, wid = tid >> 5;
        int xs = pv;
        #pragma unroll
        for (int dd = 1; dd < 32; dd <<= 1) {
            int y = __shfl_up_sync(0xffffffffu, xs, dd);
            if (lane >= dd) xs += y;
        }
        __shared__ int wsum[32];
        if (lane == 31) wsum[wid] = xs;
        __syncthreads();
        if (wid == 0) {
            int s = wsum[lane];
            int sx = s;
            #pragma unroll
            for (int dd = 1; dd < 32; dd <<= 1) {
                int y = __shfl_up_sync(0xffffffffu, sx, dd);
                if (lane >= dd) sx += y;
            }
            wsum[lane] = sx - s;
        }
        __syncthreads();
        int incl = xs + wsum[wid];
        excl = incl - pv;
        if (tid == 1023) g_bsums[bid] = incl;
    }
    gbar(0);

    {
        __shared__ int ws[4];
        int bv = 0, incl = 0;
        if (bid == 0) {
            if (tid < 128) {
                bv = (tid < SCAN_NBLK) ? __ldcg(&g_bsums[tid]) : 0;
                int lane = tid & 31, wid = tid >> 5;
                int xs = bv;
                #pragma unroll
                for (int dd = 1; dd < 32; dd <<= 1) {
                    int y = __shfl_up_sync(0xffffffffu, xs, dd);
                    if (lane >= dd) xs += y;
                }
                if (lane == 31) ws[wid] = xs;
                incl = xs;
            }
            __syncthreads();
            if (tid < 128) {
                int wid = tid >> 5;
                int off = 0;
                for (int w = 0; w < wid; w++) off += ws[w];
                incl += off;
                if (tid < SCAN_NBLK) g_bsums[tid] = incl - bv;
            }
        }
    }
    gbar(1);

    if (valid) {
        int i = bid * 1024 + tid;
        int rp = excl + __ldcg(&g_bsums[bid]);
        g_rowptr[i] = rp;
        for (int j = v; j < pv; j++) g_src[rp + j] = ZROW;   // pad slots -> zero row
        if (i == NN - 1) g_rowptr[NN] = rp + pv;
    }
    gbar(2);

    const int gt = bid * 1024 + tid;
    for (int e = gt; e < NE; e += SCAN_NBLK * 1024) {
        int c = col[e];
        int p = __ldcg(&g_rowptr[c]) + __ldcg(&g_rank[e]);
        g_src[p] = row[e] << 5;
    }
}

// ---------------- conv2 GEMM (1563 blocks; premultiplied, fp16 A from g_h1h) ----------------
__global__ __launch_bounds__(128) void k_gemm2(const float* __restrict__ W) {
    __shared__ __half Wt[64][HID + 8];
    __shared__ __half Ahs[64][HID + 8];

    for (int i = threadIdx.x; i < HID * 64; i += 128) {
        int k = i >> 6, n = i & 63;
        Wt[n][k] = __float2half(W[i]);
    }

    const int rbase = blockIdx.x * 64;
    const __half* Ah = reinterpret_cast<const __half*>(g_h1h);
    #pragma unroll
    for (int it = 0; it < 4; it++) {
        int i = it * 128 + threadIdx.x;
        int r = i >> 3, v = i & 7;
        int R = rbase + r;
        uint4 val = make_uint4(0, 0, 0, 0);
        if (R < NN) val = reinterpret_cast<const uint4*>(Ah + (size_t)R * HID)[v];
        reinterpret_cast<uint4*>(&Ahs[r][0])[v] = val;
    }
    __syncthreads();

    const int warp = threadIdx.x >> 5, lane = threadIdx.x & 31;
    const int gr = lane >> 2;
    const int kc = (lane & 3) * 2;
    const int lr0 = warp * 16 + gr, lr1 = lr0 + 8;
    const int R0 = rbase + lr0, R1 = rbase + lr1;

    float d[8][4];
    #pragma unroll
    for (int nt = 0; nt < 8; nt++)
        #pragma unroll
        for (int q = 0; q < 4; q++) d[nt][q] = 0.f;

    #pragma unroll
    for (int q = 0; q < HID / 16; q++) {
        int k0 = q * 16 + kc;
        uint32 a0 = *reinterpret_cast<const uint32*>(&Ahs[lr0][k0]);
        uint32 a1 = *reinterpret_cast<const uint32*>(&Ahs[lr1][k0]);
        uint32 a2 = *reinterpret_cast<const uint32*>(&Ahs[lr0][k0 + 8]);
        uint32 a3 = *reinterpret_cast<const uint32*>(&Ahs[lr1][k0 + 8]);
        #pragma unroll
        for (int nt = 0; nt < 8; nt++) {
            int n = nt * 8 + gr;
            uint32 b0 = *reinterpret_cast<const uint32*>(&Wt[n][k0]);
            uint32 b1 = *reinterpret_cast<const uint32*>(&Wt[n][k0 + 8]);
            mma16816(d[nt], a0, a1, a2, a3, b0, b1);
        }
    }

    float dv0 = (R0 < NN) ? g_dinv[R0] : 0.f;
    float dv1 = (R1 < NN) ? g_dinv[R1] : 0.f;
    #pragma unroll
    for (int nt = 0; nt < 8; nt++) {
        int c = nt * 8 + kc;
        *reinterpret_cast<__half2*>(&Ahs[lr0][c]) =
            __floats2half2_rn(d[nt][0] * dv0, d[nt][1] * dv0);
        *reinterpret_cast<__half2*>(&Ahs[lr1][c]) =
            __floats2half2_rn(d[nt][2] * dv1, d[nt][3] * dv1);
    }
    __syncwarp();
    __half* outp = reinterpret_cast<__half*>(g_h0h);
    #pragma unroll
    for (int rr = 0; rr < 16; rr++) {
        int R = rbase + warp * 16 + rr;
        if (R < NN) {
            uint32 v = reinterpret_cast<const uint32*>(&Ahs[warp * 16 + rr][0])[lane];
            reinterpret_cast<uint32*>(outp + (size_t)R * 64)[lane] = v;
        }
    }
}

// ---------------- GCN aggregate (unweighted, padded rows, HADD2 pairing) ----------------
__global__ __launch_bounds__(256) void k_agg(const float* __restrict__ bias) {
    int gw = (blockIdx.x * 256 + threadIdx.x) >> 5;
    int lane = threadIdx.x & 31;
    float di = g_dinv[gw];
    int beg = g_rowptr[gw], end = g_rowptr[gw + 1];   // 4-aligned

    const __half2* hin = g_h0h;
    float2 hself = __half22float2(hin[gw * 32 + lane]);
    float ax = hself.x, ay = hself.y;

    int e = beg;
    for (; e + 8 <= end; e += 8) {
        int4 pa = *reinterpret_cast<const int4*>(&g_src[e]);
        int4 pb = *reinterpret_cast<const int4*>(&g_src[e + 4]);
        __half2 v0 = __ldg(&hin[pa.x + lane]);
        __half2 v1 = __ldg(&hin[pa.y + lane]);
        __half2 v2 = __ldg(&hin[pa.z + lane]);
        __half2 v3 = __ldg(&hin[pa.w + lane]);
        __half2 v4 = __ldg(&hin[pb.x + lane]);
        __half2 v5 = __ldg(&hin[pb.y + lane]);
        __half2 v6 = __ldg(&hin[pb.z + lane]);
        __half2 v7 = __ldg(&hin[pb.w + lane]);
        float2 s0 = __half22float2(__hadd2(v0, v1));
        float2 s1 = __half22float2(__hadd2(v2, v3));
        float2 s2 = __half22float2(__hadd2(v4, v5));
        float2 s3 = __half22float2(__hadd2(v6, v7));
        ax += (s0.x + s1.x) + (s2.x + s3.x);
        ay += (s0.y + s1.y) + (s2.y + s3.y);
    }
    if (e < end) {
        int4 pa = *reinterpret_cast<const int4*>(&g_src[e]);
        __half2 v0 = __ldg(&hin[pa.x + lane]);
        __half2 v1 = __ldg(&hin[pa.y + lane]);
        __half2 v2 = __ldg(&hin[pa.z + lane]);
        __half2 v3 = __ldg(&hin[pa.w + lane]);
        float2 s0 = __half22float2(__hadd2(v0, v1));
        float2 s1 = __half22float2(__hadd2(v2, v3));
        ax += s0.x + s1.x;
        ay += s0.y + s1.y;
    }
    float2 b = reinterpret_cast<const float2*>(bias)[lane];
    float rx = fmaxf(fmaf(di, ax, b.x), 0.f);
    float ry = fmaxf(fmaf(di, ay, b.y), 0.f);
    g_h1h[gw * 32 + lane] = __floats2half2_rn(rx, ry);
}

// ---------------- edge head GEMM (1563 blocks): g_yh[r,16](fp16) = h2@Wm (+bl cols 0..7) ----------------
__global__ __launch_bounds__(128) void k_head(const float* __restrict__ Wl,
                                              const float* __restrict__ bl) {
    __shared__ __half Wt[16][HID + 8];
    __shared__ __half Ahs[64][HID + 8];

    for (int i = threadIdx.x; i < 16 * 64; i += 128) {
        int o = i >> 6, k = i & 63;
        float wv = (o < 8) ? Wl[k * 8 + o] : Wl[(64 + k) * 8 + (o - 8)];
        Wt[o][k] = __float2half(wv);
    }

    const int rbase = blockIdx.x * 64;
    const __half* Ah = reinterpret_cast<const __half*>(g_h1h);
    #pragma unroll
    for (int it = 0; it < 4; it++) {
        int i = it * 128 + threadIdx.x;
        int r = i >> 3, v = i & 7;
        int R = rbase + r;
        uint4 val = make_uint4(0, 0, 0, 0);
        if (R < NN) val = reinterpret_cast<const uint4*>(Ah + (size_t)R * HID)[v];
        reinterpret_cast<uint4*>(&Ahs[r][0])[v] = val;
    }
    __syncthreads();

    const int warp = threadIdx.x >> 5, lane = threadIdx.x & 31;
    const int gr = lane >> 2;
    const int kc = (lane & 3) * 2;
    const int lr0 = warp * 16 + gr, lr1 = lr0 + 8;
    const int R0 = rbase + lr0, R1 = rbase + lr1;

    float d[2][4];
    #pragma unroll
    for (int nt = 0; nt < 2; nt++)
        #pragma unroll
        for (int q = 0; q < 4; q++) d[nt][q] = 0.f;

    #pragma unroll
    for (int q = 0; q < HID / 16; q++) {
        int k0 = q * 16 + kc;
        uint32 a0 = *reinterpret_cast<const uint32*>(&Ahs[lr0][k0]);
        uint32 a1 = *reinterpret_cast<const uint32*>(&Ahs[lr1][k0]);
        uint32 a2 = *reinterpret_cast<const uint32*>(&Ahs[lr0][k0 + 8]);
        uint32 a3 = *reinterpret_cast<const uint32*>(&Ahs[lr1][k0 + 8]);
        #pragma unroll
        for (int nt = 0; nt < 2; nt++) {
            int n = nt * 8 + gr;
            uint32 b0 = *reinterpret_cast<const uint32*>(&Wt[n][k0]);
            uint32 b1 = *reinterpret_cast<const uint32*>(&Wt[n][k0 + 8]);
            mma16816(d[nt], a0, a1, a2, a3, b0, b1);
        }
    }

    float bx0 = __ldg(&bl[kc]), bx1 = __ldg(&bl[kc + 1]);
    if (R0 < NN) {
        *reinterpret_cast<__half2*>(&g_yh[(size_t)R0 * 16 + kc]) =
            __floats2half2_rn(d[0][0] + bx0, d[0][1] + bx1);
        *reinterpret_cast<__half2*>(&g_yh[(size_t)R0 * 16 + 8 + kc]) =
            __floats2half2_rn(d[1][0], d[1][1]);
    }
    if (R1 < NN) {
        *reinterpret_cast<__half2*>(&g_yh[(size_t)R1 * 16 + kc]) =
            __floats2half2_rn(d[0][2] + bx0, d[0][3] + bx1);
        *reinterpret_cast<__half2*>(&g_yh[(size_t)R1 * 16 + 8 + kc]) =
            __floats2half2_rn(d[1][2], d[1][3]);
    }
}

// ---------------- edge phase (fp16 y) + state cleanup for next replay ----------------
__global__ void k_edge(const int* __restrict__ row, const int* __restrict__ col,
                       float* __restrict__ out) {
    int idx = blockIdx.x * 256 + threadIdx.x;
    if (idx < NN) g_deg[idx] = 0;
    if (idx < 8) g_barc[idx] = 0;
    if (idx >= NE * 2) return;
    int e = idx >> 1, c = idx & 1;
    int r = row[e], cl = col[e];
    const __half2* a2 = reinterpret_cast<const __half2*>(&g_yh[(size_t)r * 16 + c * 4]);
    const __half2* b2 = reinterpret_cast<const __half2*>(&g_yh[(size_t)cl * 16 + 8 + c * 4]);
    __half2 a0 = a2[0], a1 = a2[1];
    __half2 b0 = b2[0], b1 = b2[1];
    float2 fa0 = __half22float2(a0), fa1 = __half22float2(a1);
    float2 fb0 = __half22float2(b0), fb1 = __half22float2(b1);
    float4 o;
    o.x = fa0.x + fb0.x;
    o.y = fa0.y + fb0.y;
    o.z = fa1.x + fb1.x;
    o.w = fa1.y + fb1.y;
    reinterpret_cast<float4*>(out)[idx] = o;
}

// ---------------- launch ----------------
extern "C" void kernel_launch(void* const* d_in, const int* in_sizes, int n_in,
                              void* d_out, int out_size) {
    const float* x  = (const float*)d_in[0];
    const int*   ei = (const int*)  d_in[1];
    const float* W1 = (const float*)d_in[2];
    const float* b1 = (const float*)d_in[3];
    const float* W2 = (const float*)d_in[4];
    const float* b2 = (const float*)d_in[5];
    const float* Wl = (const float*)d_in[6];
    const float* bl = (const float*)d_in[7];
    float* out = (float*)d_out;

    const int* row = ei;        // edge_index[0]
    const int* col = ei + NE;   // edge_index[1]

    const int DSMEM = (64 + 8 * 64) * (FIN + 8) * (int)sizeof(__half);  // 156,672 B
    static bool attr_set = false;
    if (!attr_set) {
        cudaFuncSetAttribute(k_scan_gemm, cudaFuncAttributeMaxDynamicSharedMemorySize, DSMEM);
        attr_set = true;
    }

    // hist + rank (deg zeroed by previous k_edge / initial state)
    k_hist<<<ALL_B, 1024>>>(col);

    // fused: padded scan+fill (0..97) + premultiplied GEMM1 (98..147)
    k_scan_gemm<<<ALL_B, 1024, DSMEM>>>(row, col, x, W1);

    // conv1 agg -> h1h
    k_agg<<<(NN * 32) / 256, 256>>>(b1);

    // conv2: premultiplied GEMM (h1h -> h0h) + agg (-> h1h)
    k_gemm2<<<NTILES, 128>>>(W2);
    k_agg<<<(NN * 32) / 256, 256>>>(b2);

    // edge head GEMM (h1h -> yh fp16), then per-edge sum (+cleanup)
    k_head<<<NTILES, 128>>>(Wl, bl);
    k_edge<<<(NE * 2 + 255) / 256, 256>>>(row, col, out);
}

// round 17
// speedup vs baseline: 1.0265x; 1.0114x over previous
#include <cuda_runtime.h>
#include <cuda_fp16.h>

#define NN 100000
#define NE 1600000
#define FIN 128
#define HID 64
#define SCAN_NBLK 98     // CSR-role blocks (scan chunk count: ceil(NN/1024))
#define ALL_B 148
#define GEMM_BLKS (ALL_B - SCAN_NBLK)   // 50 GEMM-role blocks
#define NTILES ((NN + 63) / 64)         // 1563 64-row tiles
#define ZROW (NN * 32)                   // pre-scaled index of the zero row

typedef unsigned int uint32;

// ---------------- scratch (device globals; no allocation allowed) ----------------
__device__ __align__(256) __half2 g_h0h[(size_t)(NN + 1) * 32];  // +1 zero row for pads
__device__ __align__(256) __half2 g_h1h[(size_t)NN * 32];
__device__ __align__(256) __half  g_yh[(size_t)NN * 16];         // edge-head partials (fp16)
__device__ __align__(256) float  g_dinv[NN];
__device__ __align__(256) int    g_deg[NN];                // zeroed by k_edge for next replay
__device__ __align__(256) int    g_rank[NE];
__device__ __align__(256) int    g_rowptr[NN + 1];
__device__ __align__(256) int    g_src[NE + 4 * NN];       // padded payload: src*32
__device__ __align__(256) int    g_bsums[128];
__device__ int g_barc[8];   // barrier counters (zeroed by k_edge)

// ---------------- software grid barrier (CSR-role blocks only: target 98) ----------------
__device__ __forceinline__ void gbar(int j) {
    __syncthreads();
    if (threadIdx.x == 0) {
        __threadfence();
        atomicAdd(&g_barc[j], 1);
        volatile int* p = &g_barc[j];
        while (*p < SCAN_NBLK) { }
        __threadfence();
    }
    __syncthreads();
}

__device__ __forceinline__ void mma16816(float d[4], uint32 a0, uint32 a1, uint32 a2,
                                         uint32 a3, uint32 b0, uint32 b1) {
    asm volatile(
        "mma.sync.aligned.m16n8k16.row.col.f32.f16.f16.f32 "
        "{%0,%1,%2,%3}, {%4,%5,%6,%7}, {%8,%9}, {%0,%1,%2,%3};"
        : "+f"(d[0]), "+f"(d[1]), "+f"(d[2]), "+f"(d[3])
        : "r"(a0), "r"(a1), "r"(a2), "r"(a3), "r"(b0), "r"(b1));
}

// ---------------- histogram + rank (full chip; deg zero on entry) ----------------
__global__ __launch_bounds__(1024) void k_hist(const int* __restrict__ col) {
    int gt = blockIdx.x * 1024 + threadIdx.x;
    for (int e = gt; e < NE; e += ALL_B * 1024)
        g_rank[e] = atomicAdd(&g_deg[col[e]], 1);
    if (blockIdx.x == 0 && threadIdx.x < 32)
        reinterpret_cast<uint32*>(g_h0h)[ZROW + threadIdx.x] = 0;
}

// ============ fused: blocks 0..97 scan+fill (padded), blocks 98..147 premul GEMM1 ============
extern __shared__ __half dsm_[];

__global__ __launch_bounds__(1024, 1) void k_scan_gemm(const int* __restrict__ row,
                                                       const int* __restrict__ col,
                                                       const float* __restrict__ x,
                                                       const float* __restrict__ W1) {
    const int tid = threadIdx.x, bid = blockIdx.x;

    if (bid >= SCAN_NBLK) {
        // ------------- GEMM1 role: g_h0h = fp16(dinv * (x @ W1)) -------------
        __half (*Wt)[FIN + 8]  = reinterpret_cast<__half(*)[FIN + 8]>(dsm_);
        __half (*Ahs)[FIN + 8] = reinterpret_cast<__half(*)[FIN + 8]>(dsm_) + 64;

        for (int i = tid; i < FIN * 64; i += 1024) {
            int k = i >> 6, n = i & 63;
            Wt[n][k] = __float2half(W1[i]);
        }
        __syncthreads();

        const int g = tid >> 7;
        const int t = tid & 127;
        const int warp = t >> 5, lane = t & 31;
        const int gr = lane >> 2;
        const int kc = (lane & 3) * 2;
        __half (*Ag)[FIN + 8] = Ahs + g * 64;
        const int barid = g + 1;

        for (int tile = (bid - SCAN_NBLK) * 8 + g; tile < NTILES; tile += GEMM_BLKS * 8) {
            const int rbase = tile * 64;
            #pragma unroll
            for (int it = 0; it < 16; it++) {
                int i = it * 128 + t;
                int r = i >> 5, v = i & 31;
                int R = rbase + r;
                float4 f = make_float4(0.f, 0.f, 0.f, 0.f);
                if (R < NN) f = reinterpret_cast<const float4*>(x + (size_t)R * FIN)[v];
                __half2 h01 = __floats2half2_rn(f.x, f.y);
                __half2 h23 = __floats2half2_rn(f.z, f.w);
                uint2 pk = make_uint2(*reinterpret_cast<uint32*>(&h01),
                                      *reinterpret_cast<uint32*>(&h23));
                *reinterpret_cast<uint2*>(&Ag[r][v * 4]) = pk;
            }
            asm volatile("bar.sync %0, 128;" :: "r"(barid) : "memory");

            const int lr0 = warp * 16 + gr, lr1 = lr0 + 8;
            const int R0 = rbase + lr0, R1 = rbase + lr1;
            float d[8][4];
            #pragma unroll
            for (int nt = 0; nt < 8; nt++)
                #pragma unroll
                for (int q = 0; q < 4; q++) d[nt][q] = 0.f;

            #pragma unroll
            for (int q = 0; q < FIN / 16; q++) {
                int k0 = q * 16 + kc;
                uint32 a0 = *reinterpret_cast<const uint32*>(&Ag[lr0][k0]);
                uint32 a1 = *reinterpret_cast<const uint32*>(&Ag[lr1][k0]);
                uint32 a2 = *reinterpret_cast<const uint32*>(&Ag[lr0][k0 + 8]);
                uint32 a3 = *reinterpret_cast<const uint32*>(&Ag[lr1][k0 + 8]);
                #pragma unroll
                for (int nt = 0; nt < 8; nt++) {
                    int n = nt * 8 + gr;
                    uint32 b0 = *reinterpret_cast<const uint32*>(&Wt[n][k0]);
                    uint32 b1 = *reinterpret_cast<const uint32*>(&Wt[n][k0 + 8]);
                    mma16816(d[nt], a0, a1, a2, a3, b0, b1);
                }
            }

            float dv0 = (R0 < NN) ? rsqrtf((float)__ldcg(&g_deg[R0]) + 1.0f) : 0.f;
            float dv1 = (R1 < NN) ? rsqrtf((float)__ldcg(&g_deg[R1]) + 1.0f) : 0.f;
            #pragma unroll
            for (int nt = 0; nt < 8; nt++) {
                int c = nt * 8 + kc;
                *reinterpret_cast<__half2*>(&Ag[lr0][c]) =
                    __floats2half2_rn(d[nt][0] * dv0, d[nt][1] * dv0);
                *reinterpret_cast<__half2*>(&Ag[lr1][c]) =
                    __floats2half2_rn(d[nt][2] * dv1, d[nt][3] * dv1);
            }
            __syncwarp();
            __half* outp = reinterpret_cast<__half*>(g_h0h);
            #pragma unroll
            for (int rr = 0; rr < 16; rr++) {
                int R = rbase + warp * 16 + rr;
                if (R < NN) {
                    uint32 v = reinterpret_cast<const uint32*>(&Ag[warp * 16 + rr][0])[lane];
                    reinterpret_cast<uint32*>(outp + (size_t)R * 64)[lane] = v;
                }
            }
            asm volatile("bar.sync %0, 128;" :: "r"(barid) : "memory");
        }
        return;
    }

    // ---------------- CSR role: dinv + padded scan + fill ----------------
    int excl = 0;
    int valid = 0;
    int v = 0, pv = 0;
    {
        int i = bid * 1024 + tid;
        valid = (i < NN);
        v = valid ? __ldcg(&g_deg[i]) : 0;
        pv = (v + 3) & ~3;
        if (valid) g_dinv[i] = rsqrtf((float)v + 1.0f);   // +1 self-loop
        int lane = tid & 31, wid = tid >> 5;
        int xs = pv;
        #pragma unroll
        for (int dd = 1; dd < 32; dd <<= 1) {
            int y = __shfl_up_sync(0xffffffffu, xs, dd);
            if (lane >= dd) xs += y;
        }
        __shared__ int wsum[32];
        if (lane == 31) wsum[wid] = xs;
        __syncthreads();
        if (wid == 0) {
            int s = wsum[lane];
            int sx = s;
            #pragma unroll
            for (int dd = 1; dd < 32; dd <<= 1) {
                int y = __shfl_up_sync(0xffffffffu, sx, dd);
                if (lane >= dd) sx += y;
            }
            wsum[lane] = sx - s;
        }
        __syncthreads();
        int incl = xs + wsum[wid];
        excl = incl - pv;
        if (tid == 1023) g_bsums[bid] = incl;
    }
    gbar(0);

    {
        __shared__ int ws[4];
        int bv = 0, incl = 0;
        if (bid == 0) {
            if (tid < 128) {
                bv = (tid < SCAN_NBLK) ? __ldcg(&g_bsums[tid]) : 0;
                int lane = tid & 31, wid = tid >> 5;
                int xs = bv;
                #pragma unroll
                for (int dd = 1; dd < 32; dd <<= 1) {
                    int y = __shfl_up_sync(0xffffffffu, xs, dd);
                    if (lane >= dd) xs += y;
                }
                if (lane == 31) ws[wid] = xs;
                incl = xs;
            }
            __syncthreads();
            if (tid < 128) {
                int wid = tid >> 5;
                int off = 0;
                for (int w = 0; w < wid; w++) off += ws[w];
                incl += off;
                if (tid < SCAN_NBLK) g_bsums[tid] = incl - bv;
            }
        }
    }
    gbar(1);

    if (valid) {
        int i = bid * 1024 + tid;
        int rp = excl + __ldcg(&g_bsums[bid]);
        g_rowptr[i] = rp;
        for (int j = v; j < pv; j++) g_src[rp + j] = ZROW;   // pad slots -> zero row
        if (i == NN - 1) g_rowptr[NN] = rp + pv;
    }
    gbar(2);

    const int gt = bid * 1024 + tid;
    for (int e = gt; e < NE; e += SCAN_NBLK * 1024) {
        int c = col[e];
        int p = __ldcg(&g_rowptr[c]) + __ldcg(&g_rank[e]);
        g_src[p] = row[e] << 5;
    }
}

// ---------------- conv2 GEMM (1563 blocks; premultiplied, fp16 A from g_h1h) ----------------
__global__ __launch_bounds__(128) void k_gemm2(const float* __restrict__ W) {
    __shared__ __half Wt[64][HID + 8];
    __shared__ __half Ahs[64][HID + 8];

    for (int i = threadIdx.x; i < HID * 64; i += 128) {
        int k = i >> 6, n = i & 63;
        Wt[n][k] = __float2half(W[i]);
    }

    const int rbase = blockIdx.x * 64;
    const __half* Ah = reinterpret_cast<const __half*>(g_h1h);
    #pragma unroll
    for (int it = 0; it < 4; it++) {
        int i = it * 128 + threadIdx.x;
        int r = i >> 3, v = i & 7;
        int R = rbase + r;
        uint4 val = make_uint4(0, 0, 0, 0);
        if (R < NN) val = reinterpret_cast<const uint4*>(Ah + (size_t)R * HID)[v];
        reinterpret_cast<uint4*>(&Ahs[r][0])[v] = val;
    }
    __syncthreads();

    const int warp = threadIdx.x >> 5, lane = threadIdx.x & 31;
    const int gr = lane >> 2;
    const int kc = (lane & 3) * 2;
    const int lr0 = warp * 16 + gr, lr1 = lr0 + 8;
    const int R0 = rbase + lr0, R1 = rbase + lr1;

    float d[8][4];
    #pragma unroll
    for (int nt = 0; nt < 8; nt++)
        #pragma unroll
        for (int q = 0; q < 4; q++) d[nt][q] = 0.f;

    #pragma unroll
    for (int q = 0; q < HID / 16; q++) {
        int k0 = q * 16 + kc;
        uint32 a0 = *reinterpret_cast<const uint32*>(&Ahs[lr0][k0]);
        uint32 a1 = *reinterpret_cast<const uint32*>(&Ahs[lr1][k0]);
        uint32 a2 = *reinterpret_cast<const uint32*>(&Ahs[lr0][k0 + 8]);
        uint32 a3 = *reinterpret_cast<const uint32*>(&Ahs[lr1][k0 + 8]);
        #pragma unroll
        for (int nt = 0; nt < 8; nt++) {
            int n = nt * 8 + gr;
            uint32 b0 = *reinterpret_cast<const uint32*>(&Wt[n][k0]);
            uint32 b1 = *reinterpret_cast<const uint32*>(&Wt[n][k0 + 8]);
            mma16816(d[nt], a0, a1, a2, a3, b0, b1);
        }
    }

    float dv0 = (R0 < NN) ? g_dinv[R0] : 0.f;
    float dv1 = (R1 < NN) ? g_dinv[R1] : 0.f;
    #pragma unroll
    for (int nt = 0; nt < 8; nt++) {
        int c = nt * 8 + kc;
        *reinterpret_cast<__half2*>(&Ahs[lr0][c]) =
            __floats2half2_rn(d[nt][0] * dv0, d[nt][1] * dv0);
        *reinterpret_cast<__half2*>(&Ahs[lr1][c]) =
            __floats2half2_rn(d[nt][2] * dv1, d[nt][3] * dv1);
    }
    __syncwarp();
    __half* outp = reinterpret_cast<__half*>(g_h0h);
    #pragma unroll
    for (int rr = 0; rr < 16; rr++) {
        int R = rbase + warp * 16 + rr;
        if (R < NN) {
            uint32 v = reinterpret_cast<const uint32*>(&Ahs[warp * 16 + rr][0])[lane];
            reinterpret_cast<uint32*>(outp + (size_t)R * 64)[lane] = v;
        }
    }
}

// ---------------- GCN aggregate: ONE WARP = TWO NODES (doubled gather MLP) ----------------
// h[c] = relu(dinv[c] * (pre[c] + sum pre[s]) + b); rows padded to multiple of 4.
__global__ __launch_bounds__(256) void k_agg(const float* __restrict__ bias) {
    int w = (blockIdx.x * 256 + threadIdx.x) >> 5;   // warp id: owns nodes 2w, 2w+1
    int lane = threadIdx.x & 31;
    const int n0 = 2 * w, n1 = 2 * w + 1;            // grid exact: 6250 blocks * 8 warps * 2

    float di0 = g_dinv[n0], di1 = g_dinv[n1];
    int e0 = g_rowptr[n0];
    int end0 = g_rowptr[n1];       // contiguous rows
    int e1 = end0;
    int end1 = g_rowptr[n1 + 1];

    const __half2* hin = g_h0h;
    float2 hs0 = __half22float2(hin[n0 * 32 + lane]);
    float2 hs1 = __half22float2(hin[n1 * 32 + lane]);
    float ax0 = hs0.x, ay0 = hs0.y;
    float ax1 = hs1.x, ay1 = hs1.y;

    // interleaved main loop: 4 gathers per node in flight (8 total)
    while (e0 + 4 <= end0 && e1 + 4 <= end1) {
        int4 pa = *reinterpret_cast<const int4*>(&g_src[e0]);
        int4 pb = *reinterpret_cast<const int4*>(&g_src[e1]);
        __half2 a0 = __ldg(&hin[pa.x + lane]);
        __half2 a1 = __ldg(&hin[pa.y + lane]);
        __half2 a2 = __ldg(&hin[pa.z + lane]);
        __half2 a3 = __ldg(&hin[pa.w + lane]);
        __half2 b0 = __ldg(&hin[pb.x + lane]);
        __half2 b1 = __ldg(&hin[pb.y + lane]);
        __half2 b2 = __ldg(&hin[pb.z + lane]);
        __half2 b3 = __ldg(&hin[pb.w + lane]);
        float2 sa0 = __half22float2(__hadd2(a0, a1));
        float2 sa1 = __half22float2(__hadd2(a2, a3));
        float2 sb0 = __half22float2(__hadd2(b0, b1));
        float2 sb1 = __half22float2(__hadd2(b2, b3));
        ax0 += sa0.x + sa1.x;
        ay0 += sa0.y + sa1.y;
        ax1 += sb0.x + sb1.x;
        ay1 += sb0.y + sb1.y;
        e0 += 4;
        e1 += 4;
    }
    // drain node 0 (4-aligned)
    for (; e0 + 4 <= end0; e0 += 4) {
        int4 pa = *reinterpret_cast<const int4*>(&g_src[e0]);
        __half2 a0 = __ldg(&hin[pa.x + lane]);
        __half2 a1 = __ldg(&hin[pa.y + lane]);
        __half2 a2 = __ldg(&hin[pa.z + lane]);
        __half2 a3 = __ldg(&hin[pa.w + lane]);
        float2 s0 = __half22float2(__hadd2(a0, a1));
        float2 s1 = __half22float2(__hadd2(a2, a3));
        ax0 += s0.x + s1.x;
        ay0 += s0.y + s1.y;
    }
    // drain node 1 (4-aligned)
    for (; e1 + 4 <= end1; e1 += 4) {
        int4 pb = *reinterpret_cast<const int4*>(&g_src[e1]);
        __half2 b0 = __ldg(&hin[pb.x + lane]);
        __half2 b1 = __ldg(&hin[pb.y + lane]);
        __half2 b2 = __ldg(&hin[pb.z + lane]);
        __half2 b3 = __ldg(&hin[pb.w + lane]);
        float2 s0 = __half22float2(__hadd2(b0, b1));
        float2 s1 = __half22float2(__hadd2(b2, b3));
        ax1 += s0.x + s1.x;
        ay1 += s0.y + s1.y;
    }

    float2 b = reinterpret_cast<const float2*>(bias)[lane];
    float r0x = fmaxf(fmaf(di0, ax0, b.x), 0.f);
    float r0y = fmaxf(fmaf(di0, ay0, b.y), 0.f);
    float r1x = fmaxf(fmaf(di1, ax1, b.x), 0.f);
    float r1y = fmaxf(fmaf(di1, ay1, b.y), 0.f);
    g_h1h[n0 * 32 + lane] = __floats2half2_rn(r0x, r0y);
    g_h1h[n1 * 32 + lane] = __floats2half2_rn(r1x, r1y);
}

// ---------------- edge head GEMM (1563 blocks): g_yh[r,16](fp16) = h2@Wm (+bl cols 0..7) ----------------
__global__ __launch_bounds__(128) void k_head(const float* __restrict__ Wl,
                                              const float* __restrict__ bl) {
    __shared__ __half Wt[16][HID + 8];
    __shared__ __half Ahs[64][HID + 8];

    for (int i = threadIdx.x; i < 16 * 64; i += 128) {
        int o = i >> 6, k = i & 63;
        float wv = (o < 8) ? Wl[k * 8 + o] : Wl[(64 + k) * 8 + (o - 8)];
        Wt[o][k] = __float2half(wv);
    }

    const int rbase = blockIdx.x * 64;
    const __half* Ah = reinterpret_cast<const __half*>(g_h1h);
    #pragma unroll
    for (int it = 0; it < 4; it++) {
        int i = it * 128 + threadIdx.x;
        int r = i >> 3, v = i & 7;
        int R = rbase + r;
        uint4 val = make_uint4(0, 0, 0, 0);
        if (R < NN) val = reinterpret_cast<const uint4*>(Ah + (size_t)R * HID)[v];
        reinterpret_cast<uint4*>(&Ahs[r][0])[v] = val;
    }
    __syncthreads();

    const int warp = threadIdx.x >> 5, lane = threadIdx.x & 31;
    const int gr = lane >> 2;
    const int kc = (lane & 3) * 2;
    const int lr0 = warp * 16 + gr, lr1 = lr0 + 8;
    const int R0 = rbase + lr0, R1 = rbase + lr1;

    float d[2][4];
    #pragma unroll
    for (int nt = 0; nt < 2; nt++)
        #pragma unroll
        for (int q = 0; q < 4; q++) d[nt][q] = 0.f;

    #pragma unroll
    for (int q = 0; q < HID / 16; q++) {
        int k0 = q * 16 + kc;
        uint32 a0 = *reinterpret_cast<const uint32*>(&Ahs[lr0][k0]);
        uint32 a1 = *reinterpret_cast<const uint32*>(&Ahs[lr1][k0]);
        uint32 a2 = *reinterpret_cast<const uint32*>(&Ahs[lr0][k0 + 8]);
        uint32 a3 = *reinterpret_cast<const uint32*>(&Ahs[lr1][k0 + 8]);
        #pragma unroll
        for (int nt = 0; nt < 2; nt++) {
            int n = nt * 8 + gr;
            uint32 b0 = *reinterpret_cast<const uint32*>(&Wt[n][k0]);
            uint32 b1 = *reinterpret_cast<const uint32*>(&Wt[n][k0 + 8]);
            mma16816(d[nt], a0, a1, a2, a3, b0, b1);
        }
    }

    float bx0 = __ldg(&bl[kc]), bx1 = __ldg(&bl[kc + 1]);
    if (R0 < NN) {
        *reinterpret_cast<__half2*>(&g_yh[(size_t)R0 * 16 + kc]) =
            __floats2half2_rn(d[0][0] + bx0, d[0][1] + bx1);
        *reinterpret_cast<__half2*>(&g_yh[(size_t)R0 * 16 + 8 + kc]) =
            __floats2half2_rn(d[1][0], d[1][1]);
    }
    if (R1 < NN) {
        *reinterpret_cast<__half2*>(&g_yh[(size_t)R1 * 16 + kc]) =
            __floats2half2_rn(d[0][2] + bx0, d[0][3] + bx1);
        *reinterpret_cast<__half2*>(&g_yh[(size_t)R1 * 16 + 8 + kc]) =
            __floats2half2_rn(d[1][2], d[1][3]);
    }
}

// ---------------- edge phase (fp16 y) + state cleanup for next replay ----------------
__global__ void k_edge(const int* __restrict__ row, const int* __restrict__ col,
                       float* __restrict__ out) {
    int idx = blockIdx.x * 256 + threadIdx.x;
    if (idx < NN) g_deg[idx] = 0;
    if (idx < 8) g_barc[idx] = 0;
    if (idx >= NE * 2) return;
    int e = idx >> 1, c = idx & 1;
    int r = row[e], cl = col[e];
    const __half2* a2 = reinterpret_cast<const __half2*>(&g_yh[(size_t)r * 16 + c * 4]);
    const __half2* b2 = reinterpret_cast<const __half2*>(&g_yh[(size_t)cl * 16 + 8 + c * 4]);
    __half2 a0 = a2[0], a1 = a2[1];
    __half2 b0 = b2[0], b1 = b2[1];
    float2 fa0 = __half22float2(a0), fa1 = __half22float2(a1);
    float2 fb0 = __half22float2(b0), fb1 = __half22float2(b1);
    float4 o;
    o.x = fa0.x + fb0.x;
    o.y = fa0.y + fb0.y;
    o.z = fa1.x + fb1.x;
    o.w = fa1.y + fb1.y;
    reinterpret_cast<float4*>(out)[idx] = o;
}

// ---------------- launch ----------------
extern "C" void kernel_launch(void* const* d_in, const int* in_sizes, int n_in,
                              void* d_out, int out_size) {
    const float* x  = (const float*)d_in[0];
    const int*   ei = (const int*)  d_in[1];
    const float* W1 = (const float*)d_in[2];
    const float* b1 = (const float*)d_in[3];
    const float* W2 = (const float*)d_in[4];
    const float* b2 = (const float*)d_in[5];
    const float* Wl = (const float*)d_in[6];
    const float* bl = (const float*)d_in[7];
    float* out = (float*)d_out;

    const int* row = ei;        // edge_index[0]
    const int* col = ei + NE;   // edge_index[1]

    const int DSMEM = (64 + 8 * 64) * (FIN + 8) * (int)sizeof(__half);  // 156,672 B
    static bool attr_set = false;
    if (!attr_set) {
        cudaFuncSetAttribute(k_scan_gemm, cudaFuncAttributeMaxDynamicSharedMemorySize, DSMEM);
        attr_set = true;
    }

    // hist + rank (deg zeroed by previous k_edge / initial state)
    k_hist<<<ALL_B, 1024>>>(col);

    // fused: padded scan+fill (0..97) + premultiplied GEMM1 (98..147)
    k_scan_gemm<<<ALL_B, 1024, DSMEM>>>(row, col, x, W1);

    // conv1 agg -> h1h   (2 nodes per warp: 6250 blocks)
    k_agg<<<NN / 16, 256>>>(b1);

    // conv2: premultiplied GEMM (h1h -> h0h) + agg (-> h1h)
    k_gemm2<<<NTILES, 128>>>(W2);
    k_agg<<<NN / 16, 256>>>(b2);

    // edge head GEMM (h1h -> yh fp16), then per-edge sum (+cleanup)
    k_head<<<NTILES, 128>>>(Wl, bl);
    k_edge<<<(NE * 2 + 255) / 256, 256>>>(row, col, out);
}